// round 5
// baseline (speedup 1.0000x reference)
#include <cuda_runtime.h>
#include <math.h>

#define NE 8
#define NC 1000
#define DFEAT 59
#define NH1 256
#define NH2 128
#define MAXB 16384

// scratch (no allocations allowed)
__device__ float g_h1[(size_t)MAXB * NH1];
__device__ float g_h2[(size_t)MAXB * NH2];

__device__ __forceinline__ float clipf(float x) {
    return fminf(fmaxf(x, -100.0f), 100.0f);
}

// log(x) for x in (0, ~1.1], positive normal floats. Polynomial on FMA pipe
// (MUFU.LG2 would bottleneck at 74/cyc chip-wide with 147M logs).
__device__ __forceinline__ float fast_log(float x) {
    int ix = __float_as_int(x);
    int e  = (ix - 0x3f3504f3) >> 23;            // m in [sqrt(1/2), sqrt(2))
    float m = __int_as_float(ix - (e << 23));
    float f = m - 1.0f;
    float z = f * f;
    float p =              7.0376836292e-2f;
    p = fmaf(p, f, -1.1514610310e-1f);
    p = fmaf(p, f,  1.1676998740e-1f);
    p = fmaf(p, f, -1.2420140846e-1f);
    p = fmaf(p, f,  1.4249322787e-1f);
    p = fmaf(p, f, -1.6668057665e-1f);
    p = fmaf(p, f,  2.0000714765e-1f);
    p = fmaf(p, f, -2.4999993993e-1f);
    p = fmaf(p, f,  3.3333331174e-1f);
    // log(1+f) = f - z/2 + f*z*P(f)
    float r = fmaf(p * z, f, fmaf(-0.5f, z, f));
    return fmaf((float)e, 0.69314718056f, r);
}

__device__ __forceinline__ float warp_sum(float v) {
    #pragma unroll
    for (int o = 16; o; o >>= 1) v += __shfl_xor_sync(0xffffffffu, v, o);
    return v;
}

// ---------------------------------------------------------------------------
// Kernel 1: feature extraction. One block per token (256 threads = 8 warps).
// ---------------------------------------------------------------------------
__global__ __launch_bounds__(256) void feat_kernel(
    const float* __restrict__ post, float* __restrict__ outFeats)
{
    __shared__ float tile[NE * NC];   // 32 KB
    __shared__ float s_mp[NC];        // 4 KB  mean over experts
    __shared__ float s_lmp[NC];       // 4 KB  log(mean + eps)
    __shared__ float red[24];
    __shared__ float s_maxp[NE];
    __shared__ float s_glob[3];       // [sum class var, sum m*lm, sum m^2]

    const int t    = blockIdx.x;
    const int tid  = threadIdx.x;
    const int lane = tid & 31;
    const int w    = tid >> 5;

    // ---- stage posterior tile (contiguous 32000 B), float4 coalesced ----
    {
        const float4* src = (const float4*)(post + (size_t)t * (NE * NC));
        float4* dst = (float4*)tile;
        #pragma unroll
        for (int i = tid; i < (NE * NC) / 4; i += 256) dst[i] = src[i];
    }
    __syncthreads();

    // ---- pass A: class-parallel; mean, log-mean, class var, mean entropy ----
    float a_var = 0.0f, a_ment = 0.0f, a_mn2 = 0.0f;
    for (int c = tid; c < NC; c += 256) {
        float s = 0.0f, ss = 0.0f;
        #pragma unroll
        for (int e = 0; e < NE; e++) {
            float v = tile[e * NC + c];
            s += v;
            ss = fmaf(v, v, ss);
        }
        float m = s * 0.125f;
        s_mp[c] = m;
        float lm = fast_log(m + 1e-8f);
        s_lmp[c] = lm;
        a_var  += (ss - 8.0f * m * m) * (1.0f / 7.0f);  // ddof=1 over 8 experts
        a_ment  = fmaf(m, lm, a_ment);
        a_mn2   = fmaf(m, m, a_mn2);
    }
    a_var  = warp_sum(a_var);
    a_ment = warp_sum(a_ment);
    a_mn2  = warp_sum(a_mn2);
    if (lane == 0) { red[w] = a_var; red[8 + w] = a_ment; red[16 + w] = a_mn2; }
    __syncthreads();
    if (tid == 0) {
        float v = 0.0f, me = 0.0f, mn2 = 0.0f;
        #pragma unroll
        for (int i = 0; i < 8; i++) { v += red[i]; me += red[8 + i]; mn2 += red[16 + i]; }
        s_glob[0] = v; s_glob[1] = me; s_glob[2] = mn2;
    }
    __syncthreads();

    // ---- pass B: warp w handles expert e = w ----
    {
        const int e = w;
        float s_plp = 0.0f, n2 = 0.0f, dot = 0.0f, klb = 0.0f;
        float t0 = -1e30f, t1 = -1e30f, t2 = -1e30f, t3 = -1e30f, t4 = -1e30f;
        for (int c = lane; c < NC; c += 32) {
            float p  = tile[e * NC + c];
            float lp = fast_log(p + 1e-8f);
            s_plp = fmaf(p, lp, s_plp);
            n2    = fmaf(p, p, n2);
            dot   = fmaf(p, s_mp[c], dot);
            klb   = fmaf(p, s_lmp[c], klb);
            // lane-local sorted top-5 insert
            if (p > t4) {
                if      (p > t0) { t4 = t3; t3 = t2; t2 = t1; t1 = t0; t0 = p; }
                else if (p > t1) { t4 = t3; t3 = t2; t2 = t1; t1 = p; }
                else if (p > t2) { t4 = t3; t3 = t2; t2 = p; }
                else if (p > t3) { t4 = t3; t3 = p; }
                else             { t4 = p; }
            }
        }
        s_plp = warp_sum(s_plp);
        n2    = warp_sum(n2);
        dot   = warp_sum(dot);
        klb   = warp_sum(klb);

        // merge lane-local top-5 lists: 5 rounds of warp argmax, winner pops
        float tk0, tk1, tk2, tk3, tk4;
        int k = 0;
        float tkl[5];
        #pragma unroll
        for (int r = 0; r < 5; r++) {
            float cand = (k == 0) ? t0 : (k == 1) ? t1 : (k == 2) ? t2
                       : (k == 3) ? t3 : (k == 4) ? t4 : -1e30f;
            float best = cand;
            int bl = lane;
            #pragma unroll
            for (int o = 16; o; o >>= 1) {
                float ov = __shfl_xor_sync(0xffffffffu, best, o);
                int   ol = __shfl_xor_sync(0xffffffffu, bl, o);
                if (ov > best || (ov == best && ol < bl)) { best = ov; bl = ol; }
            }
            tkl[r] = best;
            if (lane == bl) k++;
        }
        tk0 = tkl[0]; tk1 = tkl[1]; tk2 = tkl[2]; tk3 = tkl[3]; tk4 = tkl[4];

        if (lane == 0) {
            float mass = tk0 + tk1 + tk2 + tk3 + tk4;
            float ent  = -s_plp;
            float kl   = s_plp - klb;           // sum p*(log(p+eps)-log(mp+eps))
            float pn   = fmaxf(sqrtf(n2), 1e-8f);
            float mn   = fmaxf(sqrtf(s_glob[2]), 1e-8f);
            float cosv = dot / (pn * mn);
            float* fr = outFeats + (size_t)t * DFEAT;
            fr[0 * 8 + e] = clipf(ent);
            fr[1 * 8 + e] = clipf(mass);
            fr[2 * 8 + e] = clipf(1.0f - mass);
            fr[3 * 8 + e] = clipf(tk0);
            fr[4 * 8 + e] = clipf(tk0 - tk1);
            fr[5 * 8 + e] = clipf(cosv);
            fr[6 * 8 + e] = clipf(kl);
            s_maxp[e] = tk0;
        }
    }
    __syncthreads();

    if (tid == 0) {
        float s = 0.0f;
        #pragma unroll
        for (int e = 0; e < NE; e++) s += s_maxp[e];
        float mean = s * 0.125f;
        float ss = 0.0f;
        #pragma unroll
        for (int e = 0; e < NE; e++) { float d = s_maxp[e] - mean; ss = fmaf(d, d, ss); }
        float stdm = sqrtf(ss * (1.0f / 7.0f));   // ddof=1
        float* fr = outFeats + (size_t)t * DFEAT;
        fr[56] = clipf(-s_glob[1]);               // mean entropy
        fr[57] = clipf(s_glob[0] * (1.0f / NC));  // mean class var
        fr[58] = clipf(stdm);                     // std of max probs
    }
}

// ---------------------------------------------------------------------------
// Kernel 2: feats(59) @ W1 -> LN -> ReLU -> g_h1 (32 tokens / block)
// thread = (token group tg of 4 tokens) x (lane -> 8 columns)
// ---------------------------------------------------------------------------
__global__ __launch_bounds__(256) void mlp1_kernel(
    const float* __restrict__ feats,
    const float* __restrict__ W1, const float* __restrict__ b1,
    const float* __restrict__ g1, const float* __restrict__ be1)
{
    __shared__ float sf[32 * 60];    // feats tile, padded stride 60
    __shared__ float sh[32 * 260];   // h1 tile for LN, stride 260

    const int t0  = blockIdx.x * 32;
    const int tid = threadIdx.x;
    const int lane = tid & 31;
    const int tg   = tid >> 5;
    const int j0   = lane * 8;

    {
        const float* src = feats + (size_t)t0 * DFEAT;
        for (int i = tid; i < 32 * DFEAT; i += 256) {
            int tt = i / DFEAT, d = i - tt * DFEAT;
            sf[tt * 60 + d] = src[i];
        }
    }
    __syncthreads();

    float acc[4][8];
    #pragma unroll
    for (int a = 0; a < 4; a++)
        #pragma unroll
        for (int b = 0; b < 8; b++) acc[a][b] = 0.0f;

    #pragma unroll 2
    for (int k = 0; k < DFEAT; k++) {
        float4 wa = *(const float4*)(W1 + k * NH1 + j0);
        float4 wb = *(const float4*)(W1 + k * NH1 + j0 + 4);
        float wv[8] = {wa.x, wa.y, wa.z, wa.w, wb.x, wb.y, wb.z, wb.w};
        #pragma unroll
        for (int a = 0; a < 4; a++) {
            float f = sf[(tg * 4 + a) * 60 + k];
            #pragma unroll
            for (int b = 0; b < 8; b++) acc[a][b] = fmaf(f, wv[b], acc[a][b]);
        }
    }

    float4 ba = *(const float4*)(b1 + j0);
    float4 bb = *(const float4*)(b1 + j0 + 4);
    float bv[8] = {ba.x, ba.y, ba.z, ba.w, bb.x, bb.y, bb.z, bb.w};
    #pragma unroll
    for (int a = 0; a < 4; a++)
        #pragma unroll
        for (int b = 0; b < 8; b++)
            sh[(tg * 4 + a) * 260 + j0 + b] = acc[a][b] + bv[b];
    __syncthreads();

    // LN + ReLU: warp tg handles tokens tg*4 .. tg*4+3
    #pragma unroll
    for (int a = 0; a < 4; a++) {
        int tt = tg * 4 + a;
        float s = 0.0f;
        #pragma unroll
        for (int j = lane; j < NH1; j += 32) s += sh[tt * 260 + j];
        s = warp_sum(s);
        float mu = s * (1.0f / NH1);
        float vs = 0.0f;
        #pragma unroll
        for (int j = lane; j < NH1; j += 32) {
            float d = sh[tt * 260 + j] - mu;
            vs = fmaf(d, d, vs);
        }
        vs = warp_sum(vs);
        float inv = rsqrtf(vs * (1.0f / NH1) + 1e-5f);
        float* dst = g_h1 + (size_t)(t0 + tt) * NH1;
        #pragma unroll
        for (int j = lane; j < NH1; j += 32) {
            float x = (sh[tt * 260 + j] - mu) * inv * g1[j] + be1[j];
            dst[j] = fmaxf(x, 0.0f);
        }
    }
}

// ---------------------------------------------------------------------------
// Kernel 3: g_h1(256) @ W2 -> LN -> ReLU -> g_h2 (32 tokens / block)
// thread = (token group of 4) x (lane -> 4 columns)
// ---------------------------------------------------------------------------
__global__ __launch_bounds__(256) void mlp2_kernel(
    const float* __restrict__ W2, const float* __restrict__ b2,
    const float* __restrict__ g2, const float* __restrict__ be2)
{
    __shared__ float sh1[32 * 256];  // 32 KB; reused for h2 (32*132) after GEMM

    const int t0  = blockIdx.x * 32;
    const int tid = threadIdx.x;
    const int lane = tid & 31;
    const int tg   = tid >> 5;
    const int j0   = lane * 4;

    {
        const float4* src = (const float4*)(g_h1 + (size_t)t0 * NH1);
        float4* dst = (float4*)sh1;
        #pragma unroll
        for (int i = tid; i < (32 * NH1) / 4; i += 256) dst[i] = src[i];
    }
    __syncthreads();

    float acc[4][4];
    #pragma unroll
    for (int a = 0; a < 4; a++)
        #pragma unroll
        for (int b = 0; b < 4; b++) acc[a][b] = 0.0f;

    #pragma unroll 4
    for (int k = 0; k < NH1; k++) {
        float4 w4 = *(const float4*)(W2 + k * NH2 + j0);
        float wv[4] = {w4.x, w4.y, w4.z, w4.w};
        #pragma unroll
        for (int a = 0; a < 4; a++) {
            float f = sh1[(tg * 4 + a) * NH1 + k];
            #pragma unroll
            for (int b = 0; b < 4; b++) acc[a][b] = fmaf(f, wv[b], acc[a][b]);
        }
    }
    __syncthreads();   // everyone done reading sh1 before reuse

    float4 b4 = *(const float4*)(b2 + j0);
    float bv[4] = {b4.x, b4.y, b4.z, b4.w};
    float* sh2 = sh1;  // reuse, stride 132
    #pragma unroll
    for (int a = 0; a < 4; a++)
        #pragma unroll
        for (int b = 0; b < 4; b++)
            sh2[(tg * 4 + a) * 132 + j0 + b] = acc[a][b] + bv[b];
    __syncthreads();

    #pragma unroll
    for (int a = 0; a < 4; a++) {
        int tt = tg * 4 + a;
        float s = 0.0f;
        #pragma unroll
        for (int j = lane; j < NH2; j += 32) s += sh2[tt * 132 + j];
        s = warp_sum(s);
        float mu = s * (1.0f / NH2);
        float vs = 0.0f;
        #pragma unroll
        for (int j = lane; j < NH2; j += 32) {
            float d = sh2[tt * 132 + j] - mu;
            vs = fmaf(d, d, vs);
        }
        vs = warp_sum(vs);
        float inv = rsqrtf(vs * (1.0f / NH2) + 1e-5f);
        float* dst = g_h2 + (size_t)(t0 + tt) * NH2;
        #pragma unroll
        for (int j = lane; j < NH2; j += 32) {
            float x = (sh2[tt * 132 + j] - mu) * inv * g2[j] + be2[j];
            dst[j] = fmaxf(x, 0.0f);
        }
    }
}

// ---------------------------------------------------------------------------
// Kernel 4: g_h2(128) @ W3 + b3 -> logits; softmax -> weights.
// One warp per token, 8 warps per block.
// ---------------------------------------------------------------------------
__global__ __launch_bounds__(256) void mlp3_kernel(
    const float* __restrict__ W3, const float* __restrict__ b3,
    float* __restrict__ weights, float* __restrict__ logits)
{
    const int tid = threadIdx.x;
    const int lane = tid & 31;
    const int w = tid >> 5;
    const int t = blockIdx.x * 8 + w;

    const float* h = g_h2 + (size_t)t * NH2;
    float acc[8];
    #pragma unroll
    for (int e = 0; e < 8; e++) acc[e] = 0.0f;

    #pragma unroll
    for (int k = lane; k < NH2; k += 32) {
        float f = h[k];
        float4 wa = *(const float4*)(W3 + k * 8);
        float4 wb = *(const float4*)(W3 + k * 8 + 4);
        acc[0] = fmaf(f, wa.x, acc[0]);
        acc[1] = fmaf(f, wa.y, acc[1]);
        acc[2] = fmaf(f, wa.z, acc[2]);
        acc[3] = fmaf(f, wa.w, acc[3]);
        acc[4] = fmaf(f, wb.x, acc[4]);
        acc[5] = fmaf(f, wb.y, acc[5]);
        acc[6] = fmaf(f, wb.z, acc[6]);
        acc[7] = fmaf(f, wb.w, acc[7]);
    }
    #pragma unroll
    for (int e = 0; e < 8; e++) acc[e] = warp_sum(acc[e]);

    if (lane == 0) {
        float lg[8];
        float mx = -1e30f;
        #pragma unroll
        for (int e = 0; e < 8; e++) { lg[e] = acc[e] + b3[e]; mx = fmaxf(mx, lg[e]); }
        float ex[8];
        float s = 0.0f;
        #pragma unroll
        for (int e = 0; e < 8; e++) { ex[e] = __expf(lg[e] - mx); s += ex[e]; }
        float inv = 1.0f / s;
        #pragma unroll
        for (int e = 0; e < 8; e++) {
            logits[(size_t)t * 8 + e]  = lg[e];
            weights[(size_t)t * 8 + e] = ex[e] * inv;
        }
    }
}

// ---------------------------------------------------------------------------
extern "C" void kernel_launch(void* const* d_in, const int* in_sizes, int n_in,
                              void* d_out, int out_size)
{
    const float* post = (const float*)d_in[0];
    const float* W1   = (const float*)d_in[1];
    const float* b1   = (const float*)d_in[2];
    const float* g1   = (const float*)d_in[3];
    const float* be1  = (const float*)d_in[4];
    const float* W2   = (const float*)d_in[5];
    const float* b2   = (const float*)d_in[6];
    const float* g2   = (const float*)d_in[7];
    const float* be2  = (const float*)d_in[8];
    const float* W3   = (const float*)d_in[9];
    const float* b3   = (const float*)d_in[10];

    const int B = in_sizes[0] / (NE * NC);

    float* out     = (float*)d_out;
    float* weights = out;                       // (B, 8)
    float* logits  = out + (size_t)B * 8;       // (B, 8)
    float* feats   = out + (size_t)B * 16;      // (B, 59)

    feat_kernel<<<B, 256>>>(post, feats);
    mlp1_kernel<<<B / 32, 256>>>(feats, W1, b1, g1, be1);
    mlp2_kernel<<<B / 32, 256>>>(W2, b2, g2, be2);
    mlp3_kernel<<<B / 8, 256>>>(W3, b3, weights, logits);
}

// round 6
// speedup vs baseline: 1.0010x; 1.0010x over previous
#include <cuda_runtime.h>
#include <math.h>

#define NE 8
#define NC 1000
#define DFEAT 59
#define NH1 256
#define NH2 128
#define MAXB 16384

// scratch (no allocations allowed)
__device__ float g_h1[(size_t)MAXB * NH1];
__device__ float g_h2[(size_t)MAXB * NH2];

__device__ __forceinline__ float clipf(float x) {
    return fminf(fmaxf(x, -100.0f), 100.0f);
}

// log(x) for x in (0, ~1.1], positive normal floats. Polynomial on FMA pipe
// (MUFU.LG2 would bottleneck at 74/cyc chip-wide with 147M logs).
__device__ __forceinline__ float fast_log(float x) {
    int ix = __float_as_int(x);
    int e  = (ix - 0x3f3504f3) >> 23;            // m in [sqrt(1/2), sqrt(2))
    float m = __int_as_float(ix - (e << 23));
    float f = m - 1.0f;
    float z = f * f;
    float p =              7.0376836292e-2f;
    p = fmaf(p, f, -1.1514610310e-1f);
    p = fmaf(p, f,  1.1676998740e-1f);
    p = fmaf(p, f, -1.2420140846e-1f);
    p = fmaf(p, f,  1.4249322787e-1f);
    p = fmaf(p, f, -1.6668057665e-1f);
    p = fmaf(p, f,  2.0000714765e-1f);
    p = fmaf(p, f, -2.4999993993e-1f);
    p = fmaf(p, f,  3.3333331174e-1f);
    // log(1+f) = f - z/2 + f*z*P(f)
    float r = fmaf(p * z, f, fmaf(-0.5f, z, f));
    return fmaf((float)e, 0.69314718056f, r);
}

__device__ __forceinline__ float warp_sum(float v) {
    #pragma unroll
    for (int o = 16; o; o >>= 1) v += __shfl_xor_sync(0xffffffffu, v, o);
    return v;
}

// ---------------------------------------------------------------------------
// Kernel 1: feature extraction. One block per token (256 threads = 8 warps).
// ---------------------------------------------------------------------------
__global__ __launch_bounds__(256) void feat_kernel(
    const float* __restrict__ post, float* __restrict__ outFeats)
{
    __shared__ float tile[NE * NC];   // 32 KB
    __shared__ float s_mp[NC];        // 4 KB  mean over experts
    __shared__ float s_lmp[NC];       // 4 KB  log(mean + eps)
    __shared__ float red[24];
    __shared__ float s_maxp[NE];
    __shared__ float s_glob[3];       // [sum class var, sum m*lm, sum m^2]

    const int t    = blockIdx.x;
    const int tid  = threadIdx.x;
    const int lane = tid & 31;
    const int w    = tid >> 5;

    // ---- stage posterior tile (contiguous 32000 B), float4 coalesced ----
    {
        const float4* src = (const float4*)(post + (size_t)t * (NE * NC));
        float4* dst = (float4*)tile;
        #pragma unroll
        for (int i = tid; i < (NE * NC) / 4; i += 256) dst[i] = src[i];
    }
    __syncthreads();

    // ---- pass A: class-parallel; mean, log-mean, class var, mean entropy ----
    float a_var = 0.0f, a_ment = 0.0f, a_mn2 = 0.0f;
    for (int c = tid; c < NC; c += 256) {
        float s = 0.0f, ss = 0.0f;
        #pragma unroll
        for (int e = 0; e < NE; e++) {
            float v = tile[e * NC + c];
            s += v;
            ss = fmaf(v, v, ss);
        }
        float m = s * 0.125f;
        s_mp[c] = m;
        float lm = fast_log(m + 1e-8f);
        s_lmp[c] = lm;
        a_var  += (ss - 8.0f * m * m) * (1.0f / 7.0f);  // ddof=1 over 8 experts
        a_ment  = fmaf(m, lm, a_ment);
        a_mn2   = fmaf(m, m, a_mn2);
    }
    a_var  = warp_sum(a_var);
    a_ment = warp_sum(a_ment);
    a_mn2  = warp_sum(a_mn2);
    if (lane == 0) { red[w] = a_var; red[8 + w] = a_ment; red[16 + w] = a_mn2; }
    __syncthreads();
    if (tid == 0) {
        float v = 0.0f, me = 0.0f, mn2 = 0.0f;
        #pragma unroll
        for (int i = 0; i < 8; i++) { v += red[i]; me += red[8 + i]; mn2 += red[16 + i]; }
        s_glob[0] = v; s_glob[1] = me; s_glob[2] = mn2;
    }
    __syncthreads();

    // ---- pass B: warp w handles expert e = w ----
    {
        const int e = w;
        float s_plp = 0.0f, n2 = 0.0f, dot = 0.0f, klb = 0.0f;
        float t0 = -1e30f, t1 = -1e30f, t2 = -1e30f, t3 = -1e30f, t4 = -1e30f;
        for (int c = lane; c < NC; c += 32) {
            float p  = tile[e * NC + c];
            float lp = fast_log(p + 1e-8f);
            s_plp = fmaf(p, lp, s_plp);
            n2    = fmaf(p, p, n2);
            dot   = fmaf(p, s_mp[c], dot);
            klb   = fmaf(p, s_lmp[c], klb);
            // lane-local sorted top-5 insert
            if (p > t4) {
                if      (p > t0) { t4 = t3; t3 = t2; t2 = t1; t1 = t0; t0 = p; }
                else if (p > t1) { t4 = t3; t3 = t2; t2 = t1; t1 = p; }
                else if (p > t2) { t4 = t3; t3 = t2; t2 = p; }
                else if (p > t3) { t4 = t3; t3 = p; }
                else             { t4 = p; }
            }
        }
        s_plp = warp_sum(s_plp);
        n2    = warp_sum(n2);
        dot   = warp_sum(dot);
        klb   = warp_sum(klb);

        // merge lane-local top-5 lists: 5 rounds of warp argmax, winner pops
        float tk0, tk1, tk2, tk3, tk4;
        int k = 0;
        float tkl[5];
        #pragma unroll
        for (int r = 0; r < 5; r++) {
            float cand = (k == 0) ? t0 : (k == 1) ? t1 : (k == 2) ? t2
                       : (k == 3) ? t3 : (k == 4) ? t4 : -1e30f;
            float best = cand;
            int bl = lane;
            #pragma unroll
            for (int o = 16; o; o >>= 1) {
                float ov = __shfl_xor_sync(0xffffffffu, best, o);
                int   ol = __shfl_xor_sync(0xffffffffu, bl, o);
                if (ov > best || (ov == best && ol < bl)) { best = ov; bl = ol; }
            }
            tkl[r] = best;
            if (lane == bl) k++;
        }
        tk0 = tkl[0]; tk1 = tkl[1]; tk2 = tkl[2]; tk3 = tkl[3]; tk4 = tkl[4];

        if (lane == 0) {
            float mass = tk0 + tk1 + tk2 + tk3 + tk4;
            float ent  = -s_plp;
            float kl   = s_plp - klb;           // sum p*(log(p+eps)-log(mp+eps))
            float pn   = fmaxf(sqrtf(n2), 1e-8f);
            float mn   = fmaxf(sqrtf(s_glob[2]), 1e-8f);
            float cosv = dot / (pn * mn);
            float* fr = outFeats + (size_t)t * DFEAT;
            fr[0 * 8 + e] = clipf(ent);
            fr[1 * 8 + e] = clipf(mass);
            fr[2 * 8 + e] = clipf(1.0f - mass);
            fr[3 * 8 + e] = clipf(tk0);
            fr[4 * 8 + e] = clipf(tk0 - tk1);
            fr[5 * 8 + e] = clipf(cosv);
            fr[6 * 8 + e] = clipf(kl);
            s_maxp[e] = tk0;
        }
    }
    __syncthreads();

    if (tid == 0) {
        float s = 0.0f;
        #pragma unroll
        for (int e = 0; e < NE; e++) s += s_maxp[e];
        float mean = s * 0.125f;
        float ss = 0.0f;
        #pragma unroll
        for (int e = 0; e < NE; e++) { float d = s_maxp[e] - mean; ss = fmaf(d, d, ss); }
        float stdm = sqrtf(ss * (1.0f / 7.0f));   // ddof=1
        float* fr = outFeats + (size_t)t * DFEAT;
        fr[56] = clipf(-s_glob[1]);               // mean entropy
        fr[57] = clipf(s_glob[0] * (1.0f / NC));  // mean class var
        fr[58] = clipf(stdm);                     // std of max probs
    }
}

// ---------------------------------------------------------------------------
// Kernel 2: feats(59) @ W1 -> LN -> ReLU -> g_h1 (32 tokens / block)
// thread = (token group tg of 4 tokens) x (lane -> 8 columns)
// ---------------------------------------------------------------------------
__global__ __launch_bounds__(256) void mlp1_kernel(
    const float* __restrict__ feats,
    const float* __restrict__ W1, const float* __restrict__ b1,
    const float* __restrict__ g1, const float* __restrict__ be1)
{
    __shared__ float sf[32 * 60];    // feats tile, padded stride 60
    __shared__ float sh[32 * 260];   // h1 tile for LN, stride 260

    const int t0  = blockIdx.x * 32;
    const int tid = threadIdx.x;
    const int lane = tid & 31;
    const int tg   = tid >> 5;
    const int j0   = lane * 8;

    {
        const float* src = feats + (size_t)t0 * DFEAT;
        for (int i = tid; i < 32 * DFEAT; i += 256) {
            int tt = i / DFEAT, d = i - tt * DFEAT;
            sf[tt * 60 + d] = src[i];
        }
    }
    __syncthreads();

    float acc[4][8];
    #pragma unroll
    for (int a = 0; a < 4; a++)
        #pragma unroll
        for (int b = 0; b < 8; b++) acc[a][b] = 0.0f;

    #pragma unroll 2
    for (int k = 0; k < DFEAT; k++) {
        float4 wa = *(const float4*)(W1 + k * NH1 + j0);
        float4 wb = *(const float4*)(W1 + k * NH1 + j0 + 4);
        float wv[8] = {wa.x, wa.y, wa.z, wa.w, wb.x, wb.y, wb.z, wb.w};
        #pragma unroll
        for (int a = 0; a < 4; a++) {
            float f = sf[(tg * 4 + a) * 60 + k];
            #pragma unroll
            for (int b = 0; b < 8; b++) acc[a][b] = fmaf(f, wv[b], acc[a][b]);
        }
    }

    float4 ba = *(const float4*)(b1 + j0);
    float4 bb = *(const float4*)(b1 + j0 + 4);
    float bv[8] = {ba.x, ba.y, ba.z, ba.w, bb.x, bb.y, bb.z, bb.w};
    #pragma unroll
    for (int a = 0; a < 4; a++)
        #pragma unroll
        for (int b = 0; b < 8; b++)
            sh[(tg * 4 + a) * 260 + j0 + b] = acc[a][b] + bv[b];
    __syncthreads();

    // LN + ReLU: warp tg handles tokens tg*4 .. tg*4+3
    #pragma unroll
    for (int a = 0; a < 4; a++) {
        int tt = tg * 4 + a;
        float s = 0.0f;
        #pragma unroll
        for (int j = lane; j < NH1; j += 32) s += sh[tt * 260 + j];
        s = warp_sum(s);
        float mu = s * (1.0f / NH1);
        float vs = 0.0f;
        #pragma unroll
        for (int j = lane; j < NH1; j += 32) {
            float d = sh[tt * 260 + j] - mu;
            vs = fmaf(d, d, vs);
        }
        vs = warp_sum(vs);
        float inv = rsqrtf(vs * (1.0f / NH1) + 1e-5f);
        float* dst = g_h1 + (size_t)(t0 + tt) * NH1;
        #pragma unroll
        for (int j = lane; j < NH1; j += 32) {
            float x = (sh[tt * 260 + j] - mu) * inv * g1[j] + be1[j];
            dst[j] = fmaxf(x, 0.0f);
        }
    }
}

// ---------------------------------------------------------------------------
// Kernel 3: g_h1(256) @ W2 -> LN -> ReLU -> g_h2 (32 tokens / block)
// thread = (token group of 4) x (lane -> 4 columns)
// ---------------------------------------------------------------------------
__global__ __launch_bounds__(256) void mlp2_kernel(
    const float* __restrict__ W2, const float* __restrict__ b2,
    const float* __restrict__ g2, const float* __restrict__ be2)
{
    __shared__ float sh1[32 * 256];  // 32 KB; reused for h2 (32*132) after GEMM

    const int t0  = blockIdx.x * 32;
    const int tid = threadIdx.x;
    const int lane = tid & 31;
    const int tg   = tid >> 5;
    const int j0   = lane * 4;

    {
        const float4* src = (const float4*)(g_h1 + (size_t)t0 * NH1);
        float4* dst = (float4*)sh1;
        #pragma unroll
        for (int i = tid; i < (32 * NH1) / 4; i += 256) dst[i] = src[i];
    }
    __syncthreads();

    float acc[4][4];
    #pragma unroll
    for (int a = 0; a < 4; a++)
        #pragma unroll
        for (int b = 0; b < 4; b++) acc[a][b] = 0.0f;

    #pragma unroll 4
    for (int k = 0; k < NH1; k++) {
        float4 w4 = *(const float4*)(W2 + k * NH2 + j0);
        float wv[4] = {w4.x, w4.y, w4.z, w4.w};
        #pragma unroll
        for (int a = 0; a < 4; a++) {
            float f = sh1[(tg * 4 + a) * NH1 + k];
            #pragma unroll
            for (int b = 0; b < 4; b++) acc[a][b] = fmaf(f, wv[b], acc[a][b]);
        }
    }
    __syncthreads();   // everyone done reading sh1 before reuse

    float4 b4 = *(const float4*)(b2 + j0);
    float bv[4] = {b4.x, b4.y, b4.z, b4.w};
    float* sh2 = sh1;  // reuse, stride 132
    #pragma unroll
    for (int a = 0; a < 4; a++)
        #pragma unroll
        for (int b = 0; b < 4; b++)
            sh2[(tg * 4 + a) * 132 + j0 + b] = acc[a][b] + bv[b];
    __syncthreads();

    #pragma unroll
    for (int a = 0; a < 4; a++) {
        int tt = tg * 4 + a;
        float s = 0.0f;
        #pragma unroll
        for (int j = lane; j < NH2; j += 32) s += sh2[tt * 132 + j];
        s = warp_sum(s);
        float mu = s * (1.0f / NH2);
        float vs = 0.0f;
        #pragma unroll
        for (int j = lane; j < NH2; j += 32) {
            float d = sh2[tt * 132 + j] - mu;
            vs = fmaf(d, d, vs);
        }
        vs = warp_sum(vs);
        float inv = rsqrtf(vs * (1.0f / NH2) + 1e-5f);
        float* dst = g_h2 + (size_t)(t0 + tt) * NH2;
        #pragma unroll
        for (int j = lane; j < NH2; j += 32) {
            float x = (sh2[tt * 132 + j] - mu) * inv * g2[j] + be2[j];
            dst[j] = fmaxf(x, 0.0f);
        }
    }
}

// ---------------------------------------------------------------------------
// Kernel 4: g_h2(128) @ W3 + b3 -> logits; softmax -> weights.
// One warp per token, 8 warps per block.
// ---------------------------------------------------------------------------
__global__ __launch_bounds__(256) void mlp3_kernel(
    const float* __restrict__ W3, const float* __restrict__ b3,
    float* __restrict__ weights, float* __restrict__ logits)
{
    const int tid = threadIdx.x;
    const int lane = tid & 31;
    const int w = tid >> 5;
    const int t = blockIdx.x * 8 + w;

    const float* h = g_h2 + (size_t)t * NH2;
    float acc[8];
    #pragma unroll
    for (int e = 0; e < 8; e++) acc[e] = 0.0f;

    #pragma unroll
    for (int k = lane; k < NH2; k += 32) {
        float f = h[k];
        float4 wa = *(const float4*)(W3 + k * 8);
        float4 wb = *(const float4*)(W3 + k * 8 + 4);
        acc[0] = fmaf(f, wa.x, acc[0]);
        acc[1] = fmaf(f, wa.y, acc[1]);
        acc[2] = fmaf(f, wa.z, acc[2]);
        acc[3] = fmaf(f, wa.w, acc[3]);
        acc[4] = fmaf(f, wb.x, acc[4]);
        acc[5] = fmaf(f, wb.y, acc[5]);
        acc[6] = fmaf(f, wb.z, acc[6]);
        acc[7] = fmaf(f, wb.w, acc[7]);
    }
    #pragma unroll
    for (int e = 0; e < 8; e++) acc[e] = warp_sum(acc[e]);

    if (lane == 0) {
        float lg[8];
        float mx = -1e30f;
        #pragma unroll
        for (int e = 0; e < 8; e++) { lg[e] = acc[e] + b3[e]; mx = fmaxf(mx, lg[e]); }
        float ex[8];
        float s = 0.0f;
        #pragma unroll
        for (int e = 0; e < 8; e++) { ex[e] = __expf(lg[e] - mx); s += ex[e]; }
        float inv = 1.0f / s;
        #pragma unroll
        for (int e = 0; e < 8; e++) {
            logits[(size_t)t * 8 + e]  = lg[e];
            weights[(size_t)t * 8 + e] = ex[e] * inv;
        }
    }
}

// ---------------------------------------------------------------------------
extern "C" void kernel_launch(void* const* d_in, const int* in_sizes, int n_in,
                              void* d_out, int out_size)
{
    const float* post = (const float*)d_in[0];
    const float* W1   = (const float*)d_in[1];
    const float* b1   = (const float*)d_in[2];
    const float* g1   = (const float*)d_in[3];
    const float* be1  = (const float*)d_in[4];
    const float* W2   = (const float*)d_in[5];
    const float* b2   = (const float*)d_in[6];
    const float* g2   = (const float*)d_in[7];
    const float* be2  = (const float*)d_in[8];
    const float* W3   = (const float*)d_in[9];
    const float* b3   = (const float*)d_in[10];

    const int B = in_sizes[0] / (NE * NC);

    float* out     = (float*)d_out;
    float* weights = out;                       // (B, 8)
    float* logits  = out + (size_t)B * 8;       // (B, 8)
    float* feats   = out + (size_t)B * 16;      // (B, 59)

    feat_kernel<<<B, 256>>>(post, feats);
    mlp1_kernel<<<B / 32, 256>>>(feats, W1, b1, g1, be1);
    mlp2_kernel<<<B / 32, 256>>>(W2, b2, g2, be2);
    mlp3_kernel<<<B / 8, 256>>>(W3, b3, weights, logits);
}